// round 1
// baseline (speedup 1.0000x reference)
#include <cuda_runtime.h>
#include <math.h>

#define NN   4096
#define EMBD 32
#define BQ   8192
#define KNN  20

// Scratch (device globals; no allocation in kernel_launch)
__device__ float g_D2[(size_t)NN * NN];        // 64 MB, reused per branch
__device__ float g_norm[2 * NN];
__device__ int   g_nbr_idx[2 * NN * KNN];
__device__ float g_nbr_d2[2 * NN * KNN];

// ---------------------------------------------------------------------------
// ||e||^2 per row for both embedding tables
// ---------------------------------------------------------------------------
__global__ void norms_kernel(const float* __restrict__ e1,
                             const float* __restrict__ e2) {
    int r = blockIdx.x * blockDim.x + threadIdx.x;
    if (r >= 2 * NN) return;
    const float* e = (r < NN) ? e1 : e2;
    int row = r & (NN - 1);
    const float4* p = reinterpret_cast<const float4*>(e + (size_t)row * EMBD);
    float s = 0.f;
#pragma unroll
    for (int i = 0; i < 8; i++) {
        float4 v = p[i];
        s += v.x * v.x + v.y * v.y + v.z * v.z + v.w * v.w;
    }
    g_norm[r] = s;
}

// ---------------------------------------------------------------------------
// All-pairs squared distances for one branch: D2[i][j] = n_i + n_j - 2*dot
// fp32, 128x128 tile per CTA, 8x8 per thread, K=32 single slab.
// ---------------------------------------------------------------------------
__global__ void knn_gemm(const float* __restrict__ emb, int branch) {
    __shared__ float As[EMBD][132];   // transposed tiles, 132 pad keeps 16B align
    __shared__ float Bs[EMBD][132];

    const int tid = threadIdx.x;          // 256 threads
    const int tx = tid & 15, ty = tid >> 4;
    const int i0 = blockIdx.y * 128, j0 = blockIdx.x * 128;

    const float4* ea = reinterpret_cast<const float4*>(emb) + (size_t)i0 * 8;
    const float4* eb = reinterpret_cast<const float4*>(emb) + (size_t)j0 * 8;

#pragma unroll
    for (int l = 0; l < 4; l++) {
        int lin = l * 256 + tid;          // 1024 float4s = 128 rows x 8
        int row = lin >> 3, c4 = lin & 7;
        float4 va = ea[row * 8 + c4];
        As[c4 * 4 + 0][row] = va.x; As[c4 * 4 + 1][row] = va.y;
        As[c4 * 4 + 2][row] = va.z; As[c4 * 4 + 3][row] = va.w;
        float4 vb = eb[row * 8 + c4];
        Bs[c4 * 4 + 0][row] = vb.x; Bs[c4 * 4 + 1][row] = vb.y;
        Bs[c4 * 4 + 2][row] = vb.z; Bs[c4 * 4 + 3][row] = vb.w;
    }
    __syncthreads();

    float acc[8][8];
#pragma unroll
    for (int r = 0; r < 8; r++)
#pragma unroll
        for (int c = 0; c < 8; c++) acc[r][c] = 0.f;

#pragma unroll
    for (int k = 0; k < EMBD; k++) {
        float a_[8], b_[8];
        *reinterpret_cast<float4*>(&a_[0]) = *reinterpret_cast<const float4*>(&As[k][ty * 8]);
        *reinterpret_cast<float4*>(&a_[4]) = *reinterpret_cast<const float4*>(&As[k][ty * 8 + 4]);
        *reinterpret_cast<float4*>(&b_[0]) = *reinterpret_cast<const float4*>(&Bs[k][tx * 8]);
        *reinterpret_cast<float4*>(&b_[4]) = *reinterpret_cast<const float4*>(&Bs[k][tx * 8 + 4]);
#pragma unroll
        for (int r = 0; r < 8; r++)
#pragma unroll
            for (int c = 0; c < 8; c++) acc[r][c] = fmaf(a_[r], b_[c], acc[r][c]);
    }

    const float* nrm = g_norm + branch * NN;
    float na[8], nb[8];
#pragma unroll
    for (int r = 0; r < 8; r++) na[r] = nrm[i0 + ty * 8 + r];
#pragma unroll
    for (int c = 0; c < 8; c++) nb[c] = nrm[j0 + tx * 8 + c];

#pragma unroll
    for (int r = 0; r < 8; r++) {
        int gi = i0 + ty * 8 + r;
        float o[8];
#pragma unroll
        for (int c = 0; c < 8; c++) {
            int gj = j0 + tx * 8 + c;
            float d = na[r] + nb[c] - 2.f * acc[r][c];
            if (gi == gj) d = 3.4e38f;    // exclude self
            o[c] = d;
        }
        float* dst = g_D2 + (size_t)gi * NN + j0 + tx * 8;
        *reinterpret_cast<float4*>(dst)     = make_float4(o[0], o[1], o[2], o[3]);
        *reinterpret_cast<float4*>(dst + 4) = make_float4(o[4], o[5], o[6], o[7]);
    }
}

// ---------------------------------------------------------------------------
// Top-KNN smallest d2 per row (excluding self). One warp per row.
// Tiebreak on equal d2: prefer LARGER index (matches stable ascending argsort
// taking the upper window).
// ---------------------------------------------------------------------------
__global__ void knn_select(int branch) {
    int gw = (blockIdx.x * blockDim.x + threadIdx.x) >> 5;
    int lane = threadIdx.x & 31;
    if (gw >= NN) return;

    const float4* row = reinterpret_cast<const float4*>(g_D2 + (size_t)gw * NN);

    float best[KNN]; int bidx[KNN];
#pragma unroll
    for (int m = 0; m < KNN; m++) { best[m] = INFINITY; bidx[m] = -1; }
    float wv = INFINITY; int wi = -1, wp = 0;   // current worst in list

    for (int it = 0; it < NN / 128; ++it) {
        float4 v = row[it * 32 + lane];
        int jb = it * 128 + lane * 4;
        float d[4] = {v.x, v.y, v.z, v.w};
#pragma unroll
        for (int e = 0; e < 4; e++) {
            int j = jb + e;
            bool ins = (d[e] < wv) || (d[e] == wv && j > wi);
            if (ins) {
#pragma unroll
                for (int m = 0; m < KNN; m++)
                    if (m == wp) { best[m] = d[e]; bidx[m] = j; }
                // rescan for new worst (largest d2, tie -> smallest idx)
                wv = -INFINITY; wi = 0x7fffffff; wp = 0;
#pragma unroll
                for (int m = 0; m < KNN; m++) {
                    bool worse = (best[m] > wv) || (best[m] == wv && bidx[m] < wi);
                    if (worse) { wv = best[m]; wi = bidx[m]; wp = m; }
                }
            }
        }
    }

    // Warp merge: 20 rounds of extract-min across lanes
    for (int s = 0; s < KNN; s++) {
        float mv = INFINITY; int mi = -1, mp = -1;
#pragma unroll
        for (int m = 0; m < KNN; m++) {
            bool better = (best[m] < mv) || (best[m] == mv && bidx[m] > mi);
            if (better) { mv = best[m]; mi = bidx[m]; mp = m; }
        }
        float rv = mv; int ri = mi;
#pragma unroll
        for (int off = 16; off > 0; off >>= 1) {
            float ov = __shfl_xor_sync(0xffffffffu, rv, off);
            int   oi = __shfl_xor_sync(0xffffffffu, ri, off);
            if (ov < rv || (ov == rv && oi > ri)) { rv = ov; ri = oi; }
        }
        if (mv == rv && mi == ri) {      // winner lane pops its element
#pragma unroll
            for (int m = 0; m < KNN; m++)
                if (m == mp) best[m] = INFINITY;
        }
        if (lane == 0) {
            int o = (branch * NN + gw) * KNN + s;
            g_nbr_idx[o] = ri;
            g_nbr_d2[o] = rv;
        }
    }
}

// ---------------------------------------------------------------------------
// Per-query gather + features + MLP. One warp per query.
// ---------------------------------------------------------------------------
__device__ __forceinline__ float warp_sum(float v) {
#pragma unroll
    for (int off = 16; off > 0; off >>= 1)
        v += __shfl_xor_sync(0xffffffffu, v, off);
    return v;
}

__global__ void gather_mlp(const int* __restrict__ timev,
                           const int* __restrict__ idx1v,
                           const int* __restrict__ idx2v,
                           const float* __restrict__ residuals,
                           const float* __restrict__ means,
                           const float* __restrict__ stds,
                           const float* __restrict__ W1,
                           const float* __restrict__ b1,
                           const float* __restrict__ Wm,
                           const float* __restrict__ bm,
                           const float* __restrict__ Ws,
                           const float* __restrict__ bs,
                           float* __restrict__ out) {
    int q = (blockIdx.x * blockDim.x + threadIdx.x) >> 5;
    int lane = threadIdx.x & 31;
    if (q >= BQ) return;

    int t = timev[q], a = idx1v[q], c = idx2v[q];
    size_t base = (size_t)t * NN * NN;

    float f[8];
#pragma unroll
    for (int br = 0; br < 2; ++br) {
        int row = br ? c : a;
        float wgt = 0.f, sel = 0.f;
        if (lane < KNN) {
            int o = (br * NN + row) * KNN + lane;
            int j = g_nbr_idx[o];
            float d2 = g_nbr_d2[o];
            float sim = sqrtf(fmaxf(d2, 0.f)) + 0.001f;
            wgt = expf(-sim);
            sel = br ? residuals[base + (size_t)a * NN + j]     // f2: row context
                     : residuals[base + (size_t)j * NN + c];    // f1: column context
        }
        float sw  = warp_sum(wgt * sel);
        float wsm = warp_sum(wgt);
        float ss  = warp_sum(sel);
        float s2  = warp_sum(sel * sel);
        f[br * 3 + 0] = sw / wsm;
        f[br * 3 + 1] = wsm;
        f[br * 3 + 2] = sqrtf(fmaxf((s2 - ss * ss / (float)KNN) / (float)(KNN - 1), 0.f));
    }
    f[6] = means[base + (size_t)a * NN + c];
    f[7] = stds[base + (size_t)a * NN + c];

    float om = 0.f, osum = 0.f;
#pragma unroll
    for (int r = 0; r < 2; r++) {
        int k = lane + r * 32;
        float h = b1[k];
#pragma unroll
        for (int ff = 0; ff < 8; ++ff) h = fmaf(f[ff], W1[k * 8 + ff], h);
        h = fmaxf(h, 0.f);
        om   = fmaf(h, Wm[k], om);
        osum = fmaf(h, Ws[k], osum);
    }
    om = warp_sum(om);
    osum = warp_sum(osum);
    if (lane == 0) {
        out[q]      = om   + bm[0];
        out[BQ + q] = osum + bs[0];
    }
}

// ---------------------------------------------------------------------------
extern "C" void kernel_launch(void* const* d_in, const int* in_sizes, int n_in,
                              void* d_out, int out_size) {
    const int*   timev = (const int*)d_in[0];
    const int*   idx1  = (const int*)d_in[1];
    const int*   idx2  = (const int*)d_in[2];
    const float* resid = (const float*)d_in[3];
    const float* means = (const float*)d_in[4];
    const float* stds  = (const float*)d_in[5];
    const float* emb1  = (const float*)d_in[6];
    const float* emb2  = (const float*)d_in[7];
    const float* W1    = (const float*)d_in[8];
    const float* b1    = (const float*)d_in[9];
    const float* Wm    = (const float*)d_in[10];
    const float* bm    = (const float*)d_in[11];
    const float* Ws    = (const float*)d_in[12];
    const float* bs    = (const float*)d_in[13];
    float* out = (float*)d_out;

    norms_kernel<<<32, 256>>>(emb1, emb2);

    dim3 gg(NN / 128, NN / 128);
    // branch 0 (emb1)
    knn_gemm<<<gg, 256>>>(emb1, 0);
    knn_select<<<NN / 8, 256>>>(0);
    // branch 1 (emb2)
    knn_gemm<<<gg, 256>>>(emb2, 1);
    knn_select<<<NN / 8, 256>>>(1);

    gather_mlp<<<BQ / 8, 256>>>(timev, idx1, idx2, resid, means, stds,
                                W1, b1, Wm, bm, Ws, bs, out);
}

// round 2
// speedup vs baseline: 4.7372x; 4.7372x over previous
#include <cuda_runtime.h>
#include <math.h>
#include <stdint.h>

#define NN   4096
#define EMBD 32
#define BQ   8192
#define KNN  20
#define FULL 0xffffffffu

// Scratch (device globals; no allocation in kernel_launch)
__device__ float g_D2[(size_t)NN * NN];        // 64 MB, reused per branch
__device__ float g_norm[2 * NN];
__device__ int   g_nbr_idx[2 * NN * KNN];
__device__ float g_nbr_d2[2 * NN * KNN];

// ---------------------------------------------------------------------------
// ||e||^2 per row for both embedding tables
// ---------------------------------------------------------------------------
__global__ void norms_kernel(const float* __restrict__ e1,
                             const float* __restrict__ e2) {
    int r = blockIdx.x * blockDim.x + threadIdx.x;
    if (r >= 2 * NN) return;
    const float* e = (r < NN) ? e1 : e2;
    int row = r & (NN - 1);
    const float4* p = reinterpret_cast<const float4*>(e + (size_t)row * EMBD);
    float s = 0.f;
#pragma unroll
    for (int i = 0; i < 8; i++) {
        float4 v = p[i];
        s += v.x * v.x + v.y * v.y + v.z * v.z + v.w * v.w;
    }
    g_norm[r] = s;
}

// ---------------------------------------------------------------------------
// All-pairs squared distances, one branch. D2 is symmetric: compute only
// upper-triangle tiles (bx >= by) and write both the tile and its transpose.
// fp32, 128x128 tile per CTA, 8x8 per thread, K=32 single slab.
// ---------------------------------------------------------------------------
__global__ void knn_gemm(const float* __restrict__ emb, int branch) {
    const int bx = blockIdx.x, by = blockIdx.y;
    if (bx < by) return;                  // symmetric: skip lower triangle

    __shared__ float As[EMBD][132];
    __shared__ float Bs[EMBD][132];

    const int tid = threadIdx.x;          // 256 threads
    const int tx = tid & 15, ty = tid >> 4;
    const int i0 = by * 128, j0 = bx * 128;

    const float4* ea = reinterpret_cast<const float4*>(emb) + (size_t)i0 * 8;
    const float4* eb = reinterpret_cast<const float4*>(emb) + (size_t)j0 * 8;

#pragma unroll
    for (int l = 0; l < 4; l++) {
        int lin = l * 256 + tid;          // 1024 float4s = 128 rows x 8
        int row = lin >> 3, c4 = lin & 7;
        float4 va = ea[row * 8 + c4];
        As[c4 * 4 + 0][row] = va.x; As[c4 * 4 + 1][row] = va.y;
        As[c4 * 4 + 2][row] = va.z; As[c4 * 4 + 3][row] = va.w;
        float4 vb = eb[row * 8 + c4];
        Bs[c4 * 4 + 0][row] = vb.x; Bs[c4 * 4 + 1][row] = vb.y;
        Bs[c4 * 4 + 2][row] = vb.z; Bs[c4 * 4 + 3][row] = vb.w;
    }
    __syncthreads();

    float acc[8][8];
#pragma unroll
    for (int r = 0; r < 8; r++)
#pragma unroll
        for (int c = 0; c < 8; c++) acc[r][c] = 0.f;

#pragma unroll
    for (int k = 0; k < EMBD; k++) {
        float a_[8], b_[8];
        *reinterpret_cast<float4*>(&a_[0]) = *reinterpret_cast<const float4*>(&As[k][ty * 8]);
        *reinterpret_cast<float4*>(&a_[4]) = *reinterpret_cast<const float4*>(&As[k][ty * 8 + 4]);
        *reinterpret_cast<float4*>(&b_[0]) = *reinterpret_cast<const float4*>(&Bs[k][tx * 8]);
        *reinterpret_cast<float4*>(&b_[4]) = *reinterpret_cast<const float4*>(&Bs[k][tx * 8 + 4]);
#pragma unroll
        for (int r = 0; r < 8; r++)
#pragma unroll
            for (int c = 0; c < 8; c++) acc[r][c] = fmaf(a_[r], b_[c], acc[r][c]);
    }

    const float* nrm = g_norm + branch * NN;
    float na[8], nb[8];
#pragma unroll
    for (int r = 0; r < 8; r++) na[r] = nrm[i0 + ty * 8 + r];
#pragma unroll
    for (int c = 0; c < 8; c++) nb[c] = nrm[j0 + tx * 8 + c];

    // epilogue in-place: d2 = n_i + n_j - 2*dot ; self masked to +huge
#pragma unroll
    for (int r = 0; r < 8; r++) {
        int gi = i0 + ty * 8 + r;
#pragma unroll
        for (int c = 0; c < 8; c++) {
            int gj = j0 + tx * 8 + c;
            float d = na[r] + nb[c] - 2.f * acc[r][c];
            acc[r][c] = (gi == gj) ? 3.4e38f : d;
        }
    }

    // normal write
#pragma unroll
    for (int r = 0; r < 8; r++) {
        int gi = i0 + ty * 8 + r;
        float* dst = g_D2 + (size_t)gi * NN + j0 + tx * 8;
        *reinterpret_cast<float4*>(dst)     = make_float4(acc[r][0], acc[r][1], acc[r][2], acc[r][3]);
        *reinterpret_cast<float4*>(dst + 4) = make_float4(acc[r][4], acc[r][5], acc[r][6], acc[r][7]);
    }
    // transposed write for off-diagonal tiles
    if (bx != by) {
#pragma unroll
        for (int c = 0; c < 8; c++) {
            int gj = j0 + tx * 8 + c;
            float* dst = g_D2 + (size_t)gj * NN + i0 + ty * 8;
            *reinterpret_cast<float4*>(dst)     = make_float4(acc[0][c], acc[1][c], acc[2][c], acc[3][c]);
            *reinterpret_cast<float4*>(dst + 4) = make_float4(acc[4][c], acc[5][c], acc[6][c], acc[7][c]);
        }
    }
}

// ---------------------------------------------------------------------------
// Top-KNN smallest d2 per row. One warp per row, warp-distributed sorted
// top-32 list: one 64-bit key per lane, sorted ascending across lanes.
// key = orderable_uint(d2) << 32 | (NN-1-j)  -> ties prefer larger index,
// matching the stable ascending argsort window semantics of the reference.
// ---------------------------------------------------------------------------
__device__ __forceinline__ unsigned long long make_key(float f, int j) {
    unsigned u = __float_as_uint(f);
    u = (u & 0x80000000u) ? ~u : (u | 0x80000000u);   // monotone float->uint
    return ((unsigned long long)u << 32) | (unsigned)(NN - 1 - j);
}

__device__ __forceinline__ void sel_batch(unsigned long long k,
                                          unsigned long long& list,
                                          unsigned long long& tau,
                                          int lane) {
    unsigned m = __ballot_sync(FULL, k < tau);
    while (m) {
        int src = __ffs(m) - 1; m &= m - 1;
        unsigned long long v = __shfl_sync(FULL, k, src);
        if (v < tau) {                         // uniform across warp
            unsigned lt = __ballot_sync(FULL, list < v);
            int pos = __popc(lt);
            unsigned long long up1 = __shfl_up_sync(FULL, list, 1);
            if (lane == pos)      list = v;
            else if (lane > pos)  list = up1;
            tau = __shfl_sync(FULL, list, 31);
        }
    }
}

__global__ void knn_select(int branch) {
    int gw = blockIdx.x * (blockDim.x >> 5) + (threadIdx.x >> 5);
    int lane = threadIdx.x & 31;
    if (gw >= NN) return;

    const float4* row = reinterpret_cast<const float4*>(g_D2 + (size_t)gw * NN);

    // init list from elements j = lane*4 (component .x of iteration 0)
    float4 v = row[lane];
    int jb = lane * 4;
    unsigned long long list = make_key(v.x, jb);

    // bitonic sort 32 keys ascending across lanes
#pragma unroll
    for (int k = 2; k <= 32; k <<= 1) {
#pragma unroll
        for (int j = k >> 1; j > 0; j >>= 1) {
            unsigned long long o = __shfl_xor_sync(FULL, list, j);
            bool up = ((lane & k) == 0) || (k == 32);
            bool lower = ((lane & j) == 0);
            bool take_min = (lower == up);
            unsigned long long mn = (o < list) ? o : list;
            unsigned long long mx = (o < list) ? list : o;
            list = take_min ? mn : mx;
        }
    }
    unsigned long long tau = __shfl_sync(FULL, list, 31);

    // remaining components of iteration 0
    sel_batch(make_key(v.y, jb + 1), list, tau, lane);
    sel_batch(make_key(v.z, jb + 2), list, tau, lane);
    sel_batch(make_key(v.w, jb + 3), list, tau, lane);

    for (int it = 1; it < NN / 128; ++it) {
        v = row[it * 32 + lane];
        jb = it * 128 + lane * 4;
        sel_batch(make_key(v.x, jb + 0), list, tau, lane);
        sel_batch(make_key(v.y, jb + 1), list, tau, lane);
        sel_batch(make_key(v.z, jb + 2), list, tau, lane);
        sel_batch(make_key(v.w, jb + 3), list, tau, lane);
    }

    // lanes 0..19 hold the top-20 (ascending d2); decode and store
    if (lane < KNN) {
        unsigned lo = (unsigned)list;
        int j = NN - 1 - (int)lo;
        unsigned u = (unsigned)(list >> 32);
        float d2 = (u & 0x80000000u) ? __uint_as_float(u & 0x7fffffffu)
                                     : __uint_as_float(~u);
        int o = (branch * NN + gw) * KNN + lane;
        g_nbr_idx[o] = j;
        g_nbr_d2[o] = d2;
    }
}

// ---------------------------------------------------------------------------
// Per-query gather + features + MLP. One warp per query.
// ---------------------------------------------------------------------------
__device__ __forceinline__ float warp_sum(float v) {
#pragma unroll
    for (int off = 16; off > 0; off >>= 1)
        v += __shfl_xor_sync(FULL, v, off);
    return v;
}

__global__ void gather_mlp(const int* __restrict__ timev,
                           const int* __restrict__ idx1v,
                           const int* __restrict__ idx2v,
                           const float* __restrict__ residuals,
                           const float* __restrict__ means,
                           const float* __restrict__ stds,
                           const float* __restrict__ W1,
                           const float* __restrict__ b1,
                           const float* __restrict__ Wm,
                           const float* __restrict__ bm,
                           const float* __restrict__ Ws,
                           const float* __restrict__ bs,
                           float* __restrict__ out) {
    int q = (blockIdx.x * blockDim.x + threadIdx.x) >> 5;
    int lane = threadIdx.x & 31;
    if (q >= BQ) return;

    int t = timev[q], a = idx1v[q], c = idx2v[q];
    size_t base = (size_t)t * NN * NN;

    float f[8];
#pragma unroll
    for (int br = 0; br < 2; ++br) {
        int row = br ? c : a;
        float wgt = 0.f, sel = 0.f;
        if (lane < KNN) {
            int o = (br * NN + row) * KNN + lane;
            int j = g_nbr_idx[o];
            float d2 = g_nbr_d2[o];
            float sim = sqrtf(fmaxf(d2, 0.f)) + 0.001f;
            wgt = expf(-sim);
            sel = br ? residuals[base + (size_t)a * NN + j]     // f2: row context
                     : residuals[base + (size_t)j * NN + c];    // f1: column context
        }
        float sw  = warp_sum(wgt * sel);
        float wsm = warp_sum(wgt);
        float ss  = warp_sum(sel);
        float s2  = warp_sum(sel * sel);
        f[br * 3 + 0] = sw / wsm;
        f[br * 3 + 1] = wsm;
        f[br * 3 + 2] = sqrtf(fmaxf((s2 - ss * ss / (float)KNN) / (float)(KNN - 1), 0.f));
    }
    f[6] = means[base + (size_t)a * NN + c];
    f[7] = stds[base + (size_t)a * NN + c];

    float om = 0.f, osum = 0.f;
#pragma unroll
    for (int r = 0; r < 2; r++) {
        int k = lane + r * 32;
        float h = b1[k];
#pragma unroll
        for (int ff = 0; ff < 8; ++ff) h = fmaf(f[ff], W1[k * 8 + ff], h);
        h = fmaxf(h, 0.f);
        om   = fmaf(h, Wm[k], om);
        osum = fmaf(h, Ws[k], osum);
    }
    om = warp_sum(om);
    osum = warp_sum(osum);
    if (lane == 0) {
        out[q]      = om   + bm[0];
        out[BQ + q] = osum + bs[0];
    }
}

// ---------------------------------------------------------------------------
extern "C" void kernel_launch(void* const* d_in, const int* in_sizes, int n_in,
                              void* d_out, int out_size) {
    const int*   timev = (const int*)d_in[0];
    const int*   idx1  = (const int*)d_in[1];
    const int*   idx2  = (const int*)d_in[2];
    const float* resid = (const float*)d_in[3];
    const float* means = (const float*)d_in[4];
    const float* stds  = (const float*)d_in[5];
    const float* emb1  = (const float*)d_in[6];
    const float* emb2  = (const float*)d_in[7];
    const float* W1    = (const float*)d_in[8];
    const float* b1    = (const float*)d_in[9];
    const float* Wm    = (const float*)d_in[10];
    const float* bm    = (const float*)d_in[11];
    const float* Ws    = (const float*)d_in[12];
    const float* bs    = (const float*)d_in[13];
    float* out = (float*)d_out;

    norms_kernel<<<32, 256>>>(emb1, emb2);

    dim3 gg(NN / 128, NN / 128);
    // branch 0 (emb1)
    knn_gemm<<<gg, 256>>>(emb1, 0);
    knn_select<<<NN / 8, 256>>>(0);
    // branch 1 (emb2)
    knn_gemm<<<gg, 256>>>(emb2, 1);
    knn_select<<<NN / 8, 256>>>(1);

    gather_mlp<<<BQ / 8, 256>>>(timev, idx1, idx2, resid, means, stds,
                                W1, b1, Wm, bm, Ws, bs, out);
}